// round 3
// baseline (speedup 1.0000x reference)
#include <cuda_runtime.h>
#include <cuda_bf16.h>

// Problem constants (fixed for this dataset)
#define MAXN 100000
#define MAXE 1600000
#define INF_DIM 256     // IN = H*F = 256
#define HEADS 4
#define FDIM 64

// Scratch (device globals; no allocation allowed)
__device__ float g_feat_src[(size_t)MAXN * INF_DIM];   // [N, H*F] projected features
__device__ float g_el[MAXN * HEADS];
__device__ float g_er[MAXN * HEADS];
__device__ float g_esum[MAXN * HEADS];
__device__ float g_ex[(size_t)MAXE * HEADS];           // fallback if 'a' not in d_out
__device__ int   g_is64;                               // 1 if src/dst are int64

// Read an index from either int32 or int64 storage, clamped to [0, N)
__device__ __forceinline__ int load_idx(const void* p, int i, int is64, int N)
{
    int v = is64 ? (int)((const long long*)p)[i] : ((const int*)p)[i];
    return min(max(v, 0), N - 1);
}

// ---------------------------------------------------------------------------
// Detect index dtype: int64 values < 2^32 have zero odd 32-bit words.
// ---------------------------------------------------------------------------
__global__ void detect_kernel(const int* __restrict__ src_words)
{
    if (threadIdx.x == 0 && blockIdx.x == 0) {
        int all_zero = 1;
        #pragma unroll 1
        for (int i = 0; i < 64; i++)
            if (src_words[2 * i + 1] != 0) { all_zero = 0; break; }
        g_is64 = all_zero;
    }
}

// ---------------------------------------------------------------------------
// Fused projection GEMM: C[n, 0:256]   = feat @ W_fc^T  -> g_feat_src
//                        C[n, 256:512] = feat @ W_res^T + bias -> rst (d_out)
// 64x64 tile, BK=32, 256 threads, 4x4 per thread.
// ---------------------------------------------------------------------------
__global__ void gemm_kernel(const float* __restrict__ feat,
                            const float* __restrict__ Wfc,
                            const float* __restrict__ Wres,
                            const float* __restrict__ bias,
                            float* __restrict__ rst, int N)
{
    constexpr int BM = 64, BN = 64, BK = 32;
    __shared__ float As[BK][BM];
    __shared__ float Bs[BK][BN];

    const int m0    = blockIdx.y * BM;
    const int ocol0 = blockIdx.x * BN;            // 0..511 step 64
    const float* W  = (ocol0 < 256) ? (Wfc + (size_t)ocol0 * INF_DIM)
                                    : (Wres + (size_t)(ocol0 - 256) * INF_DIM);

    const int t  = threadIdx.x;
    const int tx = t & 15;        // 0..15 (cols)
    const int ty = t >> 4;        // 0..15 (rows)

    float acc[4][4] = {};

    for (int k0 = 0; k0 < INF_DIM; k0 += BK) {
        #pragma unroll
        for (int i = 0; i < 2; i++) {
            int idx = t + i * 256;       // 0..511
            int row = idx >> 3;          // 0..63
            int kg  = idx & 7;           // 0..7 (float4 group)
            float4 v = make_float4(0.f, 0.f, 0.f, 0.f);
            if (m0 + row < N)
                v = *(const float4*)(feat + (size_t)(m0 + row) * INF_DIM + k0 + kg * 4);
            As[kg * 4 + 0][row] = v.x;
            As[kg * 4 + 1][row] = v.y;
            As[kg * 4 + 2][row] = v.z;
            As[kg * 4 + 3][row] = v.w;
            float4 w = *(const float4*)(W + (size_t)row * INF_DIM + k0 + kg * 4);
            Bs[kg * 4 + 0][row] = w.x;
            Bs[kg * 4 + 1][row] = w.y;
            Bs[kg * 4 + 2][row] = w.z;
            Bs[kg * 4 + 3][row] = w.w;
        }
        __syncthreads();

        #pragma unroll
        for (int kk = 0; kk < BK; kk++) {
            float a[4], b[4];
            #pragma unroll
            for (int i = 0; i < 4; i++) a[i] = As[kk][ty * 4 + i];
            #pragma unroll
            for (int j = 0; j < 4; j++) b[j] = Bs[kk][tx * 4 + j];
            #pragma unroll
            for (int i = 0; i < 4; i++)
                #pragma unroll
                for (int j = 0; j < 4; j++)
                    acc[i][j] += a[i] * b[j];
        }
        __syncthreads();
    }

    #pragma unroll
    for (int i = 0; i < 4; i++) {
        int row = m0 + ty * 4 + i;
        if (row >= N) continue;
        #pragma unroll
        for (int j = 0; j < 4; j++) {
            int oc = ocol0 + tx * 4 + j;
            if (oc < 256)
                g_feat_src[(size_t)row * INF_DIM + oc] = acc[i][j];
            else
                rst[(size_t)row * INF_DIM + (oc - 256)] = acc[i][j] + bias[oc - 256];
        }
    }
}

// ---------------------------------------------------------------------------
// Per-node attention logits: el[n,h] = <feat_src[n,h,:], attn_l[h,:]>, same er.
// One warp per node.
// ---------------------------------------------------------------------------
__global__ void elr_kernel(const float* __restrict__ attn_l,
                           const float* __restrict__ attn_r, int N)
{
    int warp = (int)((blockIdx.x * (size_t)blockDim.x + threadIdx.x) >> 5);
    int lane = threadIdx.x & 31;
    if (warp >= N) return;
    const float* fs = g_feat_src + (size_t)warp * INF_DIM;
    #pragma unroll
    for (int h = 0; h < HEADS; h++) {
        float v0 = fs[h * 64 + lane];
        float v1 = fs[h * 64 + 32 + lane];
        float sl = v0 * attn_l[h * 64 + lane] + v1 * attn_l[h * 64 + 32 + lane];
        float sr = v0 * attn_r[h * 64 + lane] + v1 * attn_r[h * 64 + 32 + lane];
        #pragma unroll
        for (int o = 16; o; o >>= 1) {
            sl += __shfl_xor_sync(0xffffffffu, sl, o);
            sr += __shfl_xor_sync(0xffffffffu, sr, o);
        }
        if (lane == 0) {
            g_el[warp * HEADS + h] = sl;
            g_er[warp * HEADS + h] = sr;
        }
    }
}

__global__ void zero_kernel(int n)
{
    int t = blockIdx.x * blockDim.x + threadIdx.x;
    if (t < n) g_esum[t] = 0.f;
}

// ---------------------------------------------------------------------------
// Edge pass: e = leaky_relu(el[src] + er[dst]); ex = exp(e) (softmax is
// shift-invariant, |e| <= ~9 so no max-subtraction needed in fp32).
// Stores ex into the output 'a' region, accumulates esum[dst,h].
// ---------------------------------------------------------------------------
__global__ void edge_kernel(const void* __restrict__ src,
                            const void* __restrict__ dst,
                            float* __restrict__ aout, int E, int N)
{
    int t = blockIdx.x * blockDim.x + threadIdx.x;
    if (t >= E * HEADS) return;
    int is64 = g_is64;
    int e = t >> 2;
    int h = t & 3;
    int s = load_idx(src, e, is64, N);
    int d = load_idx(dst, e, is64, N);
    float x = g_el[s * HEADS + h] + g_er[d * HEADS + h];
    x = (x > 0.f) ? x : 0.05f * x;
    float ex = __expf(x) ;
    // use precise expf to stay well under 1e-3 rel err
    ex = expf(x);
    aout[t] = ex;
    atomicAdd(&g_esum[d * HEADS + h], ex);
}

// ---------------------------------------------------------------------------
// Normalize + SpMM: a = ex / max(esum[dst], 1e-20); rst[dst] += feat_src[src]*a
// One warp per edge; 8 strided chunks of 32 lanes.
// ---------------------------------------------------------------------------
__global__ void spmm_kernel(const void* __restrict__ src,
                            const void* __restrict__ dst,
                            float* __restrict__ aout,
                            float* __restrict__ rst, int E, int N)
{
    int wid  = (int)((blockIdx.x * (size_t)blockDim.x + threadIdx.x) >> 5);
    int lane = threadIdx.x & 31;
    if (wid >= E) return;
    int is64 = g_is64;
    int s = load_idx(src, wid, is64, N);
    int d = load_idx(dst, wid, is64, N);

    float a = 0.f;
    if (lane < HEADS) {
        float ex = aout[(size_t)wid * HEADS + lane];
        float su = g_esum[d * HEADS + lane];
        a = ex / fmaxf(su, 1e-20f);
        aout[(size_t)wid * HEADS + lane] = a;
    }

    const float* fs = g_feat_src + (size_t)s * INF_DIM;
    float* r = rst + (size_t)d * INF_DIM;
    #pragma unroll
    for (int c = 0; c < 8; c++) {
        int hf = c * 32 + lane;
        float ah = __shfl_sync(0xffffffffu, a, hf >> 6);
        atomicAdd(&r[hf], fs[hf] * ah);
    }
}

extern "C" void kernel_launch(void* const* d_in, const int* in_sizes, int n_in,
                              void* d_out, int out_size)
{
    const float* feat   = (const float*)d_in[0];
    const void*  src    = d_in[1];
    const void*  dst    = d_in[2];
    const float* Wfc    = (const float*)d_in[3];
    const float* attn_l = (const float*)d_in[4];
    const float* attn_r = (const float*)d_in[5];
    const float* Wres   = (const float*)d_in[6];
    const float* bias   = (const float*)d_in[7];

    const int N = in_sizes[0] / INF_DIM;
    const int E = in_sizes[1];

    float* rst = (float*)d_out;
    float* aout;
    if ((long long)out_size >= (long long)N * INF_DIM + (long long)E * HEADS) {
        aout = rst + (size_t)N * INF_DIM;        // 'a' is the 2nd output, concatenated
    } else {
        void* p = nullptr;
        cudaGetSymbolAddress(&p, g_ex);
        aout = (float*)p;
    }

    // 0) detect index dtype (int32 vs int64)
    detect_kernel<<<1, 32>>>((const int*)src);

    // 1) projections (rst gets residual+bias; feat_src to scratch)
    dim3 ggrid(512 / 64, (N + 63) / 64);
    gemm_kernel<<<ggrid, 256>>>(feat, Wfc, Wres, bias, rst, N);

    // 2) per-node attention logits
    elr_kernel<<<(N + 7) / 8, 256>>>(attn_l, attn_r, N);

    // 3) zero softmax denominators
    zero_kernel<<<(N * HEADS + 255) / 256, 256>>>(N * HEADS);

    // 4) edge logits + exp + denominator accumulation
    edge_kernel<<<(E * HEADS + 255) / 256, 256>>>(src, dst, aout, E, N);

    // 5) normalize + scatter aggregation into rst
    spmm_kernel<<<(E + 7) / 8, 256>>>(src, dst, aout, rst, E, N);
}

// round 4
// speedup vs baseline: 2.1036x; 2.1036x over previous
#include <cuda_runtime.h>
#include <cuda_bf16.h>

#define MAXN 100000
#define MAXE 1600000
#define INF_DIM 256     // IN = H*F = 256
#define HEADS 4
#define FDIM 64

// Scratch (device globals; no allocation allowed)
__device__ float g_feat_src[(size_t)MAXN * INF_DIM];   // [N, 256] projected features
__device__ float g_el[MAXN * HEADS];
__device__ float g_er[MAXN * HEADS];
__device__ float g_esum[MAXN * HEADS];
__device__ float g_ex[(size_t)MAXE * HEADS];           // fallback if 'a' not in d_out
__device__ int   g_is64;                               // 1 if src/dst are int64

__device__ __forceinline__ int load_idx(const void* p, int i, int is64, int N)
{
    int v = is64 ? (int)((const long long*)p)[i] : ((const int*)p)[i];
    return min(max(v, 0), N - 1);
}

__global__ void detect_kernel(const int* __restrict__ src_words)
{
    if (threadIdx.x == 0 && blockIdx.x == 0) {
        int all_zero = 1;
        #pragma unroll 1
        for (int i = 0; i < 64; i++)
            if (src_words[2 * i + 1] != 0) { all_zero = 0; break; }
        g_is64 = all_zero;
    }
}

// ---------------------------------------------------------------------------
// Tensor-core projection GEMM (bf16 split-precision, 3 mma passes):
//   C[n, 0:256]   = feat @ W_fc^T            -> g_feat_src
//   C[n, 256:512] = feat @ W_res^T + bias    -> rst (d_out)
// Block tile 64x64, BK=32, 256 threads (8 warps, 2x4), warp tile 32x16.
// ---------------------------------------------------------------------------
__device__ __forceinline__ unsigned pack_bf16x2(float lo, float hi)
{
    unsigned r;
    asm("cvt.rn.bf16x2.f32 %0, %1, %2;" : "=r"(r) : "f"(hi), "f"(lo));
    return r;
}

__device__ __forceinline__ void ldsm_x4(unsigned& r0, unsigned& r1,
                                        unsigned& r2, unsigned& r3, unsigned addr)
{
    asm volatile("ldmatrix.sync.aligned.m8n8.x4.shared.b16 {%0,%1,%2,%3}, [%4];"
                 : "=r"(r0), "=r"(r1), "=r"(r2), "=r"(r3) : "r"(addr));
}

__device__ __forceinline__ void ldsm_x2(unsigned& r0, unsigned& r1, unsigned addr)
{
    asm volatile("ldmatrix.sync.aligned.m8n8.x2.shared.b16 {%0,%1}, [%2];"
                 : "=r"(r0), "=r"(r1) : "r"(addr));
}

__device__ __forceinline__ void mma_bf16(float* c, const unsigned* a, const unsigned* b)
{
    asm volatile(
        "mma.sync.aligned.m16n8k16.row.col.f32.bf16.bf16.f32 "
        "{%0,%1,%2,%3},{%4,%5,%6,%7},{%8,%9},{%0,%1,%2,%3};"
        : "+f"(c[0]), "+f"(c[1]), "+f"(c[2]), "+f"(c[3])
        : "r"(a[0]), "r"(a[1]), "r"(a[2]), "r"(a[3]), "r"(b[0]), "r"(b[1]));
}

#define SROW 40   // smem row stride in bf16 elems (pad for conflict-free ldmatrix)

__global__ void gemm_kernel(const float* __restrict__ feat,
                            const float* __restrict__ Wfc,
                            const float* __restrict__ Wres,
                            const float* __restrict__ bias,
                            float* __restrict__ rst, int N)
{
    __shared__ __align__(16) __nv_bfloat16 Ah[64 * SROW];
    __shared__ __align__(16) __nv_bfloat16 Al[64 * SROW];
    __shared__ __align__(16) __nv_bfloat16 Bh[64 * SROW];
    __shared__ __align__(16) __nv_bfloat16 Bl[64 * SROW];

    const int t      = threadIdx.x;
    const int lane   = t & 31;
    const int warp   = t >> 5;
    const int warp_m = warp >> 2;          // 0..1  (rows, 32 each)
    const int warp_n = warp & 3;           // 0..3  (cols, 16 each)
    const int m0     = blockIdx.y * 64;
    const int ocol0  = blockIdx.x * 64;    // 0..511 step 64
    const float* W   = (ocol0 < 256) ? (Wfc + (size_t)ocol0 * INF_DIM)
                                     : (Wres + (size_t)(ocol0 - 256) * INF_DIM);

    float acc[2][2][4] = {};

    // ldmatrix source addresses (computed once)
    const int a_row = (lane & 7) + ((lane >> 3) & 1) * 8;   // 0..15
    const int a_col = (lane >> 4) * 8;                      // 0 or 8
    const int b_row = lane & 7;
    const int b_col = ((lane >> 3) & 1) * 8;                // (lanes>=16 repeat; ignored by x2)

    unsigned sAh = (unsigned)__cvta_generic_to_shared(Ah);
    unsigned sAl = (unsigned)__cvta_generic_to_shared(Al);
    unsigned sBh = (unsigned)__cvta_generic_to_shared(Bh);
    unsigned sBl = (unsigned)__cvta_generic_to_shared(Bl);

    for (int k0 = 0; k0 < INF_DIM; k0 += 32) {
        // ---- load + split 64x32 fp32 tiles into bf16 hi/lo smem ----
        #pragma unroll
        for (int i = 0; i < 2; i++) {
            int linear = t + i * 256;       // 0..511
            int row = linear >> 3;          // 0..63
            int kq  = (linear & 7) * 4;     // 0,4,..,28
            // A (feat)
            float4 v = make_float4(0.f, 0.f, 0.f, 0.f);
            if (m0 + row < N)
                v = *(const float4*)(feat + (size_t)(m0 + row) * INF_DIM + k0 + kq);
            unsigned h01 = pack_bf16x2(v.x, v.y);
            unsigned h23 = pack_bf16x2(v.z, v.w);
            float rx = v.x - __uint_as_float(h01 << 16);
            float ry = v.y - __uint_as_float(h01 & 0xffff0000u);
            float rz = v.z - __uint_as_float(h23 << 16);
            float rw = v.w - __uint_as_float(h23 & 0xffff0000u);
            *(uint2*)&Ah[row * SROW + kq] = make_uint2(h01, h23);
            *(uint2*)&Al[row * SROW + kq] = make_uint2(pack_bf16x2(rx, ry), pack_bf16x2(rz, rw));
            // B (W rows = output cols)
            float4 w = *(const float4*)(W + (size_t)row * INF_DIM + k0 + kq);
            unsigned wh01 = pack_bf16x2(w.x, w.y);
            unsigned wh23 = pack_bf16x2(w.z, w.w);
            float sx = w.x - __uint_as_float(wh01 << 16);
            float sy = w.y - __uint_as_float(wh01 & 0xffff0000u);
            float sz = w.z - __uint_as_float(wh23 << 16);
            float sw = w.w - __uint_as_float(wh23 & 0xffff0000u);
            *(uint2*)&Bh[row * SROW + kq] = make_uint2(wh01, wh23);
            *(uint2*)&Bl[row * SROW + kq] = make_uint2(pack_bf16x2(sx, sy), pack_bf16x2(sz, sw));
        }
        __syncthreads();

        // ---- 2 k16-steps of mma ----
        #pragma unroll
        for (int kh = 0; kh < 2; kh++) {
            unsigned aH[2][4], aL[2][4], bH[2][2], bL[2][2];
            #pragma unroll
            for (int tm = 0; tm < 2; tm++) {
                int off = ((warp_m * 32 + tm * 16 + a_row) * SROW + kh * 16 + a_col) * 2;
                ldsm_x4(aH[tm][0], aH[tm][1], aH[tm][2], aH[tm][3], sAh + off);
                ldsm_x4(aL[tm][0], aL[tm][1], aL[tm][2], aL[tm][3], sAl + off);
            }
            #pragma unroll
            for (int tn = 0; tn < 2; tn++) {
                int off = ((warp_n * 16 + tn * 8 + b_row) * SROW + kh * 16 + b_col) * 2;
                ldsm_x2(bH[tn][0], bH[tn][1], sBh + off);
                ldsm_x2(bL[tn][0], bL[tn][1], sBl + off);
            }
            #pragma unroll
            for (int tm = 0; tm < 2; tm++)
                #pragma unroll
                for (int tn = 0; tn < 2; tn++) {
                    mma_bf16(acc[tm][tn], aH[tm], bH[tn]);
                    mma_bf16(acc[tm][tn], aL[tm], bH[tn]);
                    mma_bf16(acc[tm][tn], aH[tm], bL[tn]);
                }
        }
        __syncthreads();
    }

    // ---- epilogue ----
    #pragma unroll
    for (int tm = 0; tm < 2; tm++) {
        int rbase = m0 + warp_m * 32 + tm * 16 + (lane >> 2);
        #pragma unroll
        for (int tn = 0; tn < 2; tn++) {
            int c = ocol0 + warp_n * 16 + tn * 8 + (lane & 3) * 2;
            #pragma unroll
            for (int half = 0; half < 2; half++) {
                int r = rbase + half * 8;
                if (r >= N) continue;
                float v0 = acc[tm][tn][half * 2 + 0];
                float v1 = acc[tm][tn][half * 2 + 1];
                if (c < 256) {
                    float2* p = (float2*)(g_feat_src + (size_t)r * INF_DIM + c);
                    *p = make_float2(v0, v1);
                } else {
                    float2* p = (float2*)(rst + (size_t)r * INF_DIM + (c - 256));
                    *p = make_float2(v0 + __ldg(bias + c - 256), v1 + __ldg(bias + c - 255));
                }
            }
        }
    }
}

// ---------------------------------------------------------------------------
// Per-node attention logits + zero esum. One warp per node.
// ---------------------------------------------------------------------------
__global__ void elr_kernel(const float* __restrict__ attn_l,
                           const float* __restrict__ attn_r, int N)
{
    int node = (int)((blockIdx.x * (size_t)blockDim.x + threadIdx.x) >> 5);
    int lane = threadIdx.x & 31;
    if (node >= N) return;
    const float* fs = g_feat_src + (size_t)node * INF_DIM;
    #pragma unroll
    for (int h = 0; h < HEADS; h++) {
        float v0 = fs[h * 64 + lane];
        float v1 = fs[h * 64 + 32 + lane];
        float sl = v0 * attn_l[h * 64 + lane] + v1 * attn_l[h * 64 + 32 + lane];
        float sr = v0 * attn_r[h * 64 + lane] + v1 * attn_r[h * 64 + 32 + lane];
        #pragma unroll
        for (int o = 16; o; o >>= 1) {
            sl += __shfl_xor_sync(0xffffffffu, sl, o);
            sr += __shfl_xor_sync(0xffffffffu, sr, o);
        }
        if (lane == 0) {
            g_el[node * HEADS + h] = sl;
            g_er[node * HEADS + h] = sr;
        }
    }
    if (lane < HEADS) g_esum[node * HEADS + lane] = 0.f;
}

// ---------------------------------------------------------------------------
// Edge pass: one thread per edge; float4 el/er; vector RED into esum.
// Softmax is shift-invariant and |e| <= ~9, so exp without max-subtraction.
// ---------------------------------------------------------------------------
__device__ __forceinline__ float lrelu_exp(float x)
{
    x = (x > 0.f) ? x : 0.05f * x;
    return expf(x);
}

__global__ void edge_kernel(const void* __restrict__ src,
                            const void* __restrict__ dst,
                            float* __restrict__ aout, int E, int N)
{
    int e = blockIdx.x * blockDim.x + threadIdx.x;
    if (e >= E) return;
    int is64 = g_is64;
    int s = load_idx(src, e, is64, N);
    int d = load_idx(dst, e, is64, N);
    float4 el = *(const float4*)(g_el + s * HEADS);
    float4 er = *(const float4*)(g_er + d * HEADS);
    float4 ex;
    ex.x = lrelu_exp(el.x + er.x);
    ex.y = lrelu_exp(el.y + er.y);
    ex.z = lrelu_exp(el.z + er.z);
    ex.w = lrelu_exp(el.w + er.w);
    *(float4*)(aout + (size_t)e * HEADS) = ex;
    asm volatile("red.global.add.v4.f32 [%0], {%1,%2,%3,%4};"
                 :: "l"(g_esum + d * HEADS), "f"(ex.x), "f"(ex.y), "f"(ex.z), "f"(ex.w)
                 : "memory");
}

// ---------------------------------------------------------------------------
// Normalize + SpMM: warp per edge; float4 loads + vector RED into rst.
// ---------------------------------------------------------------------------
__global__ void spmm_kernel(const void* __restrict__ src,
                            const void* __restrict__ dst,
                            float* __restrict__ aout,
                            float* __restrict__ rst, int E, int N)
{
    int e    = (int)((blockIdx.x * (size_t)blockDim.x + threadIdx.x) >> 5);
    int lane = threadIdx.x & 31;
    if (e >= E) return;
    int is64 = g_is64;
    int s = load_idx(src, e, is64, N);
    int d = load_idx(dst, e, is64, N);

    float a = 0.f;
    if (lane < HEADS) {
        float ex = aout[(size_t)e * HEADS + lane];
        float su = g_esum[d * HEADS + lane];
        a = ex / fmaxf(su, 1e-20f);
        aout[(size_t)e * HEADS + lane] = a;
    }

    const float4* fs4 = (const float4*)(g_feat_src + (size_t)s * INF_DIM);
    float4*       r4  = (float4*)(rst + (size_t)d * INF_DIM);
    #pragma unroll
    for (int it = 0; it < 2; it++) {
        int i = it * 32 + lane;                         // float4 index 0..63
        float ah = __shfl_sync(0xffffffffu, a, i >> 4); // head = i/16
        float4 v = fs4[i];
        asm volatile("red.global.add.v4.f32 [%0], {%1,%2,%3,%4};"
                     :: "l"(r4 + i), "f"(v.x * ah), "f"(v.y * ah), "f"(v.z * ah), "f"(v.w * ah)
                     : "memory");
    }
}

extern "C" void kernel_launch(void* const* d_in, const int* in_sizes, int n_in,
                              void* d_out, int out_size)
{
    const float* feat   = (const float*)d_in[0];
    const void*  src    = d_in[1];
    const void*  dst    = d_in[2];
    const float* Wfc    = (const float*)d_in[3];
    const float* attn_l = (const float*)d_in[4];
    const float* attn_r = (const float*)d_in[5];
    const float* Wres   = (const float*)d_in[6];
    const float* bias   = (const float*)d_in[7];

    const int N = in_sizes[0] / INF_DIM;
    const int E = in_sizes[1];

    float* rst = (float*)d_out;
    float* aout;
    if ((long long)out_size >= (long long)N * INF_DIM + (long long)E * HEADS) {
        aout = rst + (size_t)N * INF_DIM;        // 'a' is the 2nd output, concatenated
    } else {
        void* p = nullptr;
        cudaGetSymbolAddress(&p, g_ex);
        aout = (float*)p;
    }

    // 0) detect index dtype (int32 vs int64)
    detect_kernel<<<1, 32>>>((const int*)src);

    // 1) projections (rst gets residual+bias; feat_src to scratch)
    dim3 ggrid(512 / 64, (N + 63) / 64);
    gemm_kernel<<<ggrid, 256>>>(feat, Wfc, Wres, bias, rst, N);

    // 2) per-node attention logits + esum zeroing
    elr_kernel<<<(N + 7) / 8, 256>>>(attn_l, attn_r, N);

    // 3) edge logits + exp + denominator accumulation
    edge_kernel<<<(E + 255) / 256, 256>>>(src, dst, aout, E, N);

    // 4) normalize + scatter aggregation into rst
    spmm_kernel<<<(E + 7) / 8, 256>>>(src, dst, aout, rst, E, N);
}

// round 5
// speedup vs baseline: 2.4806x; 1.1792x over previous
#include <cuda_runtime.h>
#include <cuda_bf16.h>

#define MAXN 100000
#define MAXE 1600000
#define INF_DIM 256     // IN = H*F = 256
#define HEADS 4

// Scratch (device globals; no allocation allowed)
__device__ float g_feat_src[(size_t)MAXN * INF_DIM];
__device__ float g_el[MAXN * HEADS];
__device__ float g_er[MAXN * HEADS];
__device__ float g_esum[MAXN * HEADS];
__device__ float g_ex[(size_t)MAXE * HEADS];   // fallback if 'a' not in d_out
__device__ int   g_is64;
// CSR scratch
__device__ int g_cnt[MAXN];
__device__ int g_off[MAXN];
__device__ int g_cur[MAXN];
__device__ int g_csr[MAXE];
__device__ int g_part[128];

__device__ __forceinline__ int load_idx(const void* p, int i, int is64, int N)
{
    int v = is64 ? (int)((const long long*)p)[i] : ((const int*)p)[i];
    return min(max(v, 0), N - 1);
}

__global__ void detect_kernel(const int* __restrict__ src_words)
{
    if (threadIdx.x == 0 && blockIdx.x == 0) {
        int all_zero = 1;
        #pragma unroll 1
        for (int i = 0; i < 64; i++)
            if (src_words[2 * i + 1] != 0) { all_zero = 0; break; }
        g_is64 = all_zero;
    }
}

// ---------------------------------------------------------------------------
// Tensor-core projection GEMM (bf16 split-precision, 3 mma passes):
//   blockIdx.x==0: C = feat @ W_fc^T          -> g_feat_src
//   blockIdx.x==1: C = feat @ W_res^T + bias  -> rst
// Block tile 64x256, BK=16, 256 threads (8 warps 2x4), warp tile 32x64.
// ---------------------------------------------------------------------------
__device__ __forceinline__ unsigned pack_bf16x2(float lo, float hi)
{
    unsigned r;
    asm("cvt.rn.bf16x2.f32 %0, %1, %2;" : "=r"(r) : "f"(hi), "f"(lo));
    return r;
}

__device__ __forceinline__ void ldsm_x4(unsigned& r0, unsigned& r1,
                                        unsigned& r2, unsigned& r3, unsigned addr)
{
    asm volatile("ldmatrix.sync.aligned.m8n8.x4.shared.b16 {%0,%1,%2,%3}, [%4];"
                 : "=r"(r0), "=r"(r1), "=r"(r2), "=r"(r3) : "r"(addr));
}

__device__ __forceinline__ void mma_bf16(float* c, const unsigned* a, const unsigned* b)
{
    asm volatile(
        "mma.sync.aligned.m16n8k16.row.col.f32.bf16.bf16.f32 "
        "{%0,%1,%2,%3},{%4,%5,%6,%7},{%8,%9},{%0,%1,%2,%3};"
        : "+f"(c[0]), "+f"(c[1]), "+f"(c[2]), "+f"(c[3])
        : "r"(a[0]), "r"(a[1]), "r"(a[2]), "r"(a[3]), "r"(b[0]), "r"(b[1]));
}

#define SRA 24   // smem row stride (bf16) for A tiles: 16 + 8 pad, conflict-free
#define SRB 24   // same for B tiles

// split float4 into bf16 hi pair / lo pair
__device__ __forceinline__ void split4(float4 v, uint2& hi, uint2& lo)
{
    unsigned h01 = pack_bf16x2(v.x, v.y);
    unsigned h23 = pack_bf16x2(v.z, v.w);
    float rx = v.x - __uint_as_float(h01 << 16);
    float ry = v.y - __uint_as_float(h01 & 0xffff0000u);
    float rz = v.z - __uint_as_float(h23 << 16);
    float rw = v.w - __uint_as_float(h23 & 0xffff0000u);
    hi = make_uint2(h01, h23);
    lo = make_uint2(pack_bf16x2(rx, ry), pack_bf16x2(rz, rw));
}

__global__ void gemm_kernel(const float* __restrict__ feat,
                            const float* __restrict__ Wfc,
                            const float* __restrict__ Wres,
                            const float* __restrict__ bias,
                            float* __restrict__ rst, int N)
{
    __shared__ __align__(16) __nv_bfloat16 Ah[64 * SRA];
    __shared__ __align__(16) __nv_bfloat16 Al[64 * SRA];
    __shared__ __align__(16) __nv_bfloat16 Bh[256 * SRB];
    __shared__ __align__(16) __nv_bfloat16 Bl[256 * SRB];

    const int t      = threadIdx.x;
    const int lane   = t & 31;
    const int warp   = t >> 5;
    const int warp_m = warp >> 2;          // 0..1  (32 rows each)
    const int warp_n = warp & 3;           // 0..3  (64 cols each)
    const int m0     = blockIdx.y * 64;
    const bool isfc  = (blockIdx.x == 0);
    const float* W   = isfc ? Wfc : Wres;

    float acc[2][8][4] = {};

    const int arow = t >> 2;              // 0..63
    const int akq  = (t & 3) * 4;         // 0,4,8,12

    // prefetch registers
    float4 pa;
    float4 pb[4];
    {
        pa = make_float4(0.f, 0.f, 0.f, 0.f);
        if (m0 + arow < N) pa = *(const float4*)(feat + (size_t)(m0 + arow) * INF_DIM + akq);
        #pragma unroll
        for (int i = 0; i < 4; i++) {
            int lin = t + i * 256;
            pb[i] = *(const float4*)(W + (size_t)(lin >> 2) * INF_DIM + (lin & 3) * 4);
        }
    }

    // ldmatrix lane addressing
    const int a_row = (lane & 7) + ((lane >> 3) & 1) * 8;   // 0..15
    const int a_col = (lane >> 4) * 8;                      // 0 or 8
    const int b_row = (lane & 7) + ((lane >> 4) & 1) * 8;   // 0..15
    const int b_col = ((lane >> 3) & 1) * 8;                // 0 or 8

    unsigned sAh = (unsigned)__cvta_generic_to_shared(Ah);
    unsigned sAl = (unsigned)__cvta_generic_to_shared(Al);
    unsigned sBh = (unsigned)__cvta_generic_to_shared(Bh);
    unsigned sBl = (unsigned)__cvta_generic_to_shared(Bl);

    for (int k0 = 0; k0 < INF_DIM; k0 += 16) {
        // ---- store prefetched tile to smem (with hi/lo split) ----
        {
            uint2 hi, lo;
            split4(pa, hi, lo);
            *(uint2*)&Ah[arow * SRA + akq] = hi;
            *(uint2*)&Al[arow * SRA + akq] = lo;
            #pragma unroll
            for (int i = 0; i < 4; i++) {
                int lin = t + i * 256;
                int brow = lin >> 2, bkq = (lin & 3) * 4;
                split4(pb[i], hi, lo);
                *(uint2*)&Bh[brow * SRB + bkq] = hi;
                *(uint2*)&Bl[brow * SRB + bkq] = lo;
            }
        }
        __syncthreads();

        // ---- prefetch next tile ----
        if (k0 + 16 < INF_DIM) {
            pa = make_float4(0.f, 0.f, 0.f, 0.f);
            if (m0 + arow < N)
                pa = *(const float4*)(feat + (size_t)(m0 + arow) * INF_DIM + k0 + 16 + akq);
            #pragma unroll
            for (int i = 0; i < 4; i++) {
                int lin = t + i * 256;
                pb[i] = *(const float4*)(W + (size_t)(lin >> 2) * INF_DIM + k0 + 16 + (lin & 3) * 4);
            }
        }

        // ---- fragments + mma ----
        unsigned aH[2][4], aL[2][4], bH[8][2], bL[8][2];
        #pragma unroll
        for (int tm = 0; tm < 2; tm++) {
            int off = ((warp_m * 32 + tm * 16 + a_row) * SRA + a_col) * 2;
            ldsm_x4(aH[tm][0], aH[tm][1], aH[tm][2], aH[tm][3], sAh + off);
            ldsm_x4(aL[tm][0], aL[tm][1], aL[tm][2], aL[tm][3], sAl + off);
        }
        #pragma unroll
        for (int gp = 0; gp < 4; gp++) {
            int off = ((warp_n * 64 + gp * 16 + b_row) * SRB + b_col) * 2;
            ldsm_x4(bH[2*gp][0], bH[2*gp][1], bH[2*gp+1][0], bH[2*gp+1][1], sBh + off);
            ldsm_x4(bL[2*gp][0], bL[2*gp][1], bL[2*gp+1][0], bL[2*gp+1][1], sBl + off);
        }
        #pragma unroll
        for (int tm = 0; tm < 2; tm++)
            #pragma unroll
            for (int ng = 0; ng < 8; ng++) {
                mma_bf16(acc[tm][ng], aH[tm], bH[ng]);
                mma_bf16(acc[tm][ng], aL[tm], bH[ng]);
                mma_bf16(acc[tm][ng], aH[tm], bL[ng]);
            }
        __syncthreads();
    }

    // ---- epilogue ----
    float* outp = isfc ? g_feat_src : rst;
    #pragma unroll
    for (int tm = 0; tm < 2; tm++) {
        int rbase = m0 + warp_m * 32 + tm * 16 + (lane >> 2);
        #pragma unroll
        for (int ng = 0; ng < 8; ng++) {
            int c = warp_n * 64 + ng * 8 + (lane & 3) * 2;
            #pragma unroll
            for (int half = 0; half < 2; half++) {
                int r = rbase + half * 8;
                if (r >= N) continue;
                float v0 = acc[tm][ng][half * 2 + 0];
                float v1 = acc[tm][ng][half * 2 + 1];
                if (!isfc) { v0 += __ldg(bias + c); v1 += __ldg(bias + c + 1); }
                *(float2*)(outp + (size_t)r * INF_DIM + c) = make_float2(v0, v1);
            }
        }
    }
}

// ---------------------------------------------------------------------------
// Per-node attention logits + zero esum/cnt. One warp per node.
// ---------------------------------------------------------------------------
__global__ void elr_kernel(const float* __restrict__ attn_l,
                           const float* __restrict__ attn_r, int N)
{
    int node = (int)((blockIdx.x * (size_t)blockDim.x + threadIdx.x) >> 5);
    int lane = threadIdx.x & 31;
    if (node >= N) return;
    const float* fs = g_feat_src + (size_t)node * INF_DIM;
    #pragma unroll
    for (int h = 0; h < HEADS; h++) {
        float v0 = fs[h * 64 + lane];
        float v1 = fs[h * 64 + 32 + lane];
        float sl = v0 * attn_l[h * 64 + lane] + v1 * attn_l[h * 64 + 32 + lane];
        float sr = v0 * attn_r[h * 64 + lane] + v1 * attn_r[h * 64 + 32 + lane];
        #pragma unroll
        for (int o = 16; o; o >>= 1) {
            sl += __shfl_xor_sync(0xffffffffu, sl, o);
            sr += __shfl_xor_sync(0xffffffffu, sr, o);
        }
        if (lane == 0) {
            g_el[node * HEADS + h] = sl;
            g_er[node * HEADS + h] = sr;
        }
    }
    if (lane < HEADS) g_esum[node * HEADS + lane] = 0.f;
    if (lane == 8) g_cnt[node] = 0;
}

// ---------------------------------------------------------------------------
// Edge pass: ex = exp(leaky_relu(el[src]+er[dst])); accumulate esum + degree.
// ---------------------------------------------------------------------------
__device__ __forceinline__ float lrelu_exp(float x)
{
    x = (x > 0.f) ? x : 0.05f * x;
    return expf(x);
}

__global__ void edge_kernel(const void* __restrict__ src,
                            const void* __restrict__ dst,
                            float* __restrict__ aout, int E, int N)
{
    int e = blockIdx.x * blockDim.x + threadIdx.x;
    if (e >= E) return;
    int is64 = g_is64;
    int s = load_idx(src, e, is64, N);
    int d = load_idx(dst, e, is64, N);
    float4 el = *(const float4*)(g_el + s * HEADS);
    float4 er = *(const float4*)(g_er + d * HEADS);
    float4 ex;
    ex.x = lrelu_exp(el.x + er.x);
    ex.y = lrelu_exp(el.y + er.y);
    ex.z = lrelu_exp(el.z + er.z);
    ex.w = lrelu_exp(el.w + er.w);
    *(float4*)(aout + (size_t)e * HEADS) = ex;
    asm volatile("red.global.add.v4.f32 [%0], {%1,%2,%3,%4};"
                 :: "l"(g_esum + d * HEADS), "f"(ex.x), "f"(ex.y), "f"(ex.z), "f"(ex.w)
                 : "memory");
    atomicAdd(&g_cnt[d], 1);
}

// ---------------------------------------------------------------------------
// CSR build: block scan (1024/block) -> scan of partials -> offsets, then scatter
// ---------------------------------------------------------------------------
__global__ void scan1_kernel(int N)
{
    __shared__ int s[1024];
    int t = threadIdx.x;
    int i = blockIdx.x * 1024 + t;
    int v = (i < N) ? g_cnt[i] : 0;
    s[t] = v;
    __syncthreads();
    #pragma unroll
    for (int o = 1; o < 1024; o <<= 1) {
        int x = (t >= o) ? s[t - o] : 0;
        __syncthreads();
        s[t] += x;
        __syncthreads();
    }
    if (i < N) g_off[i] = s[t];             // inclusive within block
    if (t == 1023) g_part[blockIdx.x] = s[1023];
}

__global__ void scan2_kernel(int nb)
{
    __shared__ int s[128];
    int t = threadIdx.x;
    int v = (t < nb) ? g_part[t] : 0;
    s[t] = v;
    __syncthreads();
    #pragma unroll
    for (int o = 1; o < 128; o <<= 1) {
        int x = (t >= o) ? s[t - o] : 0;
        __syncthreads();
        s[t] += x;
        __syncthreads();
    }
    if (t < nb) g_part[t] = s[t] - v;       // exclusive
}

__global__ void scan3_kernel(int N)
{
    int i = blockIdx.x * 1024 + threadIdx.x;
    if (i < N) {
        int excl = g_off[i] - g_cnt[i] + g_part[blockIdx.x];
        g_off[i] = excl;
        g_cur[i] = excl;
    }
}

__global__ void scatter_kernel(const void* __restrict__ dst, int E, int N)
{
    int e = blockIdx.x * blockDim.x + threadIdx.x;
    if (e >= E) return;
    int d = load_idx(dst, e, g_is64, N);
    int pos = atomicAdd(&g_cur[d], 1);
    g_csr[pos] = e;
}

// ---------------------------------------------------------------------------
// Aggregation: warp per dst node. Accumulate sum_e a[e]*feat_src[src[e]] in
// registers; single read-modify-write of rst row. Also writes normalized a.
// ---------------------------------------------------------------------------
__global__ void aggregate_kernel(const void* __restrict__ src,
                                 float* __restrict__ aout,
                                 float* __restrict__ rst, int N)
{
    int n    = (int)((blockIdx.x * (size_t)blockDim.x + threadIdx.x) >> 5);
    int lane = threadIdx.x & 31;
    if (n >= N) return;
    int is64  = g_is64;
    int start = g_off[n];
    int cnt   = g_cnt[n];

    float su = 1.f;
    if (lane < HEADS) su = fmaxf(g_esum[n * HEADS + lane], 1e-20f);

    float4 accA = make_float4(0.f, 0.f, 0.f, 0.f);
    float4 accB = make_float4(0.f, 0.f, 0.f, 0.f);
    int hA = lane >> 4;        // head of float4-idx lane    (0 or 1)
    int hB = 2 + hA;           // head of float4-idx lane+32 (2 or 3)

    for (int j = 0; j < cnt; j++) {
        int e = g_csr[start + j];
        int s = load_idx(src, e, is64, N);
        float av = 0.f;
        if (lane < HEADS) {
            av = aout[(size_t)e * HEADS + lane] / su;
            aout[(size_t)e * HEADS + lane] = av;
        }
        float aA = __shfl_sync(0xffffffffu, av, hA);
        float aB = __shfl_sync(0xffffffffu, av, hB);
        const float4* fs4 = (const float4*)(g_feat_src + (size_t)s * INF_DIM);
        float4 v = fs4[lane];
        float4 w = fs4[lane + 32];
        accA.x += v.x * aA; accA.y += v.y * aA; accA.z += v.z * aA; accA.w += v.w * aA;
        accB.x += w.x * aB; accB.y += w.y * aB; accB.z += w.z * aB; accB.w += w.w * aB;
    }

    float4* r4 = (float4*)(rst + (size_t)n * INF_DIM);
    if (cnt > 0) {
        float4 r = r4[lane];
        r.x += accA.x; r.y += accA.y; r.z += accA.z; r.w += accA.w;
        r4[lane] = r;
        float4 q = r4[lane + 32];
        q.x += accB.x; q.y += accB.y; q.z += accB.z; q.w += accB.w;
        r4[lane + 32] = q;
    }
}

extern "C" void kernel_launch(void* const* d_in, const int* in_sizes, int n_in,
                              void* d_out, int out_size)
{
    const float* feat   = (const float*)d_in[0];
    const void*  src    = d_in[1];
    const void*  dst    = d_in[2];
    const float* Wfc    = (const float*)d_in[3];
    const float* attn_l = (const float*)d_in[4];
    const float* attn_r = (const float*)d_in[5];
    const float* Wres   = (const float*)d_in[6];
    const float* bias   = (const float*)d_in[7];

    const int N = in_sizes[0] / INF_DIM;
    const int E = in_sizes[1];

    float* rst = (float*)d_out;
    float* aout;
    if ((long long)out_size >= (long long)N * INF_DIM + (long long)E * HEADS) {
        aout = rst + (size_t)N * INF_DIM;
    } else {
        void* p = nullptr;
        cudaGetSymbolAddress(&p, g_ex);
        aout = (float*)p;
    }

    const int nb = (N + 1023) / 1024;

    detect_kernel<<<1, 32>>>((const int*)src);

    dim3 ggrid(2, (N + 63) / 64);
    gemm_kernel<<<ggrid, 256>>>(feat, Wfc, Wres, bias, rst, N);

    elr_kernel<<<(N + 7) / 8, 256>>>(attn_l, attn_r, N);

    edge_kernel<<<(E + 255) / 256, 256>>>(src, dst, aout, E, N);

    scan1_kernel<<<nb, 1024>>>(N);
    scan2_kernel<<<1, 128>>>(nb);
    scan3_kernel<<<nb, 1024>>>(N);
    scatter_kernel<<<(E + 255) / 256, 256>>>(dst, E, N);

    aggregate_kernel<<<(N + 7) / 8, 256>>>(src, aout, rst, N);
}